// round 10
// baseline (speedup 1.0000x reference)
#include <cuda_runtime.h>
#include <cuda_bf16.h>
#include <mma.h>
#include <cstdint>

using namespace nvcuda;

#define B_    16
#define S_    16
#define D_    4096
#define H_    32
#define KV_   8
#define HD_   128
#define T_    256
#define KVLEN 4096
#define STARTP 4080
#define NQKV  6144

// ----------------------------- device scratch ------------------------------
__device__ float g_qkv[T_ * NQKV];
__device__ float g_attn[T_ * D_];
__device__ float g_part[2 * T_ * NQKV];

// ----------------------------- helpers ---------------------------------
__device__ __forceinline__ uint32_t smem_u32(const void* p) {
    uint32_t a;
    asm("{ .reg .u64 t; cvta.to.shared.u64 t, %1; cvt.u32.u64 %0, t; }" : "=r"(a) : "l"(p));
    return a;
}
__device__ __forceinline__ void cp16(uint32_t dst, const void* src) {
    asm volatile("cp.async.cg.shared.global [%0], [%1], 16;" :: "r"(dst), "l"(src));
}
__device__ __forceinline__ void cp_commit() { asm volatile("cp.async.commit_group;" ::: "memory"); }
template<int N> __device__ __forceinline__ void cp_wait() {
    asm volatile("cp.async.wait_group %0;" :: "n"(N) : "memory");
}
#define NBAR_SYNC(id, cnt)   asm volatile("bar.sync %0, %1;"   :: "r"(id), "r"(cnt) : "memory")
#define NBAR_ARRIVE(id, cnt) asm volatile("bar.arrive %0, %1;" :: "r"(id), "r"(cnt) : "memory")

__device__ __forceinline__ float to_tf32(float x) { return wmma::__float_to_tf32(x); }

template<class Frag>
__device__ __forceinline__ void round_frag(Frag& f) {
#pragma unroll
    for (int i = 0; i < f.num_elements; i++) f.x[i] = to_tf32(f.x[i]);
}

// ---------------------------------------------------------------------------
// tf32 GEMM, split-K=2 (unchanged from R8, passing)
// ---------------------------------------------------------------------------
#define GBK 64
#define GLDA 68
#define GLDB 132
#define G_A_FLOATS (64 * GLDA)
#define G_STAGE_FLOATS (G_A_FLOATS + GBK * GLDB)
#define G_SMEM (2 * G_STAGE_FLOATS * 4)

__global__ __launch_bounds__(256, 2) void gemm_splitk(
    const float* __restrict__ A,
    const float* __restrict__ w0, const float* __restrict__ w1, const float* __restrict__ w2,
    float* __restrict__ Cpart, int Nt, int K, int qkv_mode)
{
    extern __shared__ __align__(16) float sm[];
    float* stage[2] = { sm, sm + G_STAGE_FLOATS };

    const int tid  = threadIdx.x;
    const int warp = tid >> 5;
    const int wm   = warp >> 2;
    const int wn   = warp & 3;
    const int m0 = blockIdx.y * 64;
    const int n0 = blockIdx.x * 128;
    const int kb = blockIdx.z * (K / 2);
    const int NC = (K / 2) / GBK;

    float* Cp = Cpart + (size_t)blockIdx.z * T_ * Nt;

    const float* Bsrc; int bstride;
    if (qkv_mode) {
        if (n0 < 4096)      { Bsrc = w0 + n0;          bstride = 4096; }
        else if (n0 < 5120) { Bsrc = w1 + (n0 - 4096); bstride = 1024; }
        else                { Bsrc = w2 + (n0 - 5120); bstride = 1024; }
    } else {
        Bsrc = w0 + n0; bstride = Nt;
    }

    const uint32_t sa[2] = { smem_u32(stage[0]), smem_u32(stage[1]) };

    auto load_tile = [&](int c, int b) {
        const int k0 = kb + c * GBK;
        const uint32_t st = sa[b];
        const uint32_t stB = st + G_A_FLOATS * 4;
#pragma unroll
        for (int i = tid; i < 1024; i += 256) {
            int r = i >> 4, c4 = (i & 15) << 2;
            cp16(st + (uint32_t)(r * GLDA + c4) * 4u, A + (size_t)(m0 + r) * K + k0 + c4);
        }
#pragma unroll
        for (int i = tid; i < 2048; i += 256) {
            int r = i >> 5, c4 = (i & 31) << 2;
            cp16(stB + (uint32_t)(r * GLDB + c4) * 4u, Bsrc + (size_t)(k0 + r) * bstride + c4);
        }
        cp_commit();
    };

    wmma::fragment<wmma::accumulator, 16, 16, 8, float> acc[2][2];
#pragma unroll
    for (int i = 0; i < 2; i++)
#pragma unroll
        for (int j = 0; j < 2; j++) wmma::fill_fragment(acc[i][j], 0.0f);

    load_tile(0, 0);
    load_tile(1, 1);

    for (int c = 0; c < NC; c++) {
        const int b = c & 1;
        if (c + 1 < NC) cp_wait<1>(); else cp_wait<0>();
        __syncthreads();

        const float* As = stage[b];
        const float* Bs = stage[b] + G_A_FLOATS;
#pragma unroll
        for (int kk = 0; kk < GBK; kk += 8) {
            wmma::fragment<wmma::matrix_a, 16, 16, 8, wmma::precision::tf32, wmma::row_major> a[2];
            wmma::fragment<wmma::matrix_b, 16, 16, 8, wmma::precision::tf32, wmma::row_major> bf[2];
#pragma unroll
            for (int i = 0; i < 2; i++) {
                wmma::load_matrix_sync(a[i], As + (wm * 32 + i * 16) * GLDA + kk, GLDA);
                round_frag(a[i]);
            }
#pragma unroll
            for (int j = 0; j < 2; j++) {
                wmma::load_matrix_sync(bf[j], Bs + kk * GLDB + wn * 32 + j * 16, GLDB);
                round_frag(bf[j]);
            }
#pragma unroll
            for (int i = 0; i < 2; i++)
#pragma unroll
                for (int j = 0; j < 2; j++)
                    wmma::mma_sync(acc[i][j], a[i], bf[j], acc[i][j]);
        }
        __syncthreads();
        if (c + 2 < NC) load_tile(c + 2, b);
    }

    float* Cs = sm;
#pragma unroll
    for (int i = 0; i < 2; i++)
#pragma unroll
        for (int j = 0; j < 2; j++)
            wmma::store_matrix_sync(Cs + (wm * 32 + i * 16) * GLDB + wn * 32 + j * 16,
                                    acc[i][j], GLDB, wmma::mem_row_major);
    __syncthreads();
    for (int i = tid; i < 64 * 32; i += 256) {
        int r = i >> 5, c4 = (i & 31) << 2;
        float4 v = *reinterpret_cast<float4*>(Cs + r * GLDB + c4);
        *reinterpret_cast<float4*>(Cp + (size_t)(m0 + r) * Nt + n0 + c4) = v;
    }
}

// ---------------------------------------------------------------------------
// qkv_finish (ranged): g_qkv = part0 + part1 + bias, RoPE fused
// ---------------------------------------------------------------------------
__global__ void qkv_finish(const float* __restrict__ bq, const float* __restrict__ bk,
                           const float* __restrict__ bv,
                           const float* __restrict__ fc, const float* __restrict__ fs,
                           int i0)
{
    const int N4 = NQKV / 4;
    int i = i0 + blockIdx.x * blockDim.x + threadIdx.x;
    if (i >= T_ * N4) return;
    int m = i / N4, n4 = (i % N4) * 4;
    size_t idx = (size_t)m * NQKV + n4;

    float4 a = *reinterpret_cast<const float4*>(g_part + idx);
    float4 b = *reinterpret_cast<const float4*>(g_part + (size_t)T_ * NQKV + idx);
    float4 bb;
    if (n4 < 4096)      bb = *reinterpret_cast<const float4*>(bq + n4);
    else if (n4 < 5120) bb = *reinterpret_cast<const float4*>(bk + n4 - 4096);
    else                bb = *reinterpret_cast<const float4*>(bv + n4 - 5120);
    float4 v;
    v.x = a.x + b.x + bb.x; v.y = a.y + b.y + bb.y;
    v.z = a.z + b.z + bb.z; v.w = a.w + b.w + bb.w;

    if (n4 < 5120) {
        int s = m & 15;
        int c0 = (n4 & 127) >> 1;
        float co0 = fc[s * 64 + c0],     sn0 = fs[s * 64 + c0];
        float co1 = fc[s * 64 + c0 + 1], sn1 = fs[s * 64 + c0 + 1];
        float rx = v.x * co0 - v.y * sn0;
        float ry = v.x * sn0 + v.y * co0;
        float rz = v.z * co1 - v.w * sn1;
        float rw = v.z * sn1 + v.w * co1;
        v.x = rx; v.y = ry; v.z = rz; v.w = rw;
    }
    *reinterpret_cast<float4*>(g_qkv + idx) = v;
}

__global__ void o_finish(const float* __restrict__ bo, float* __restrict__ out)
{
    int i = blockIdx.x * blockDim.x + threadIdx.x;
    if (i >= T_ * D_ / 4) return;
    int n4 = (i % (D_ / 4)) * 4;
    size_t idx = (size_t)i * 4;
    float4 a = *reinterpret_cast<const float4*>(g_part + idx);
    float4 b = *reinterpret_cast<const float4*>(g_part + (size_t)T_ * D_ + idx);
    float4 bb = *reinterpret_cast<const float4*>(bo + n4);
    float4 v;
    v.x = a.x + b.x + bb.x; v.y = a.y + b.y + bb.y;
    v.z = a.z + b.z + bb.z; v.w = a.w + b.w + bb.w;
    *reinterpret_cast<float4*>(out + idx) = v;
}

// ---------------------------------------------------------------------------
// attention: warp-specialized producer(QK+exp) / consumer(PV), 512 threads.
// Publish: producer bar.arrive / consumer bar.sync on barrier 1+buf.
// Recycle: consumer bar.arrive / producer bar.sync on barrier 3+buf.
// ---------------------------------------------------------------------------
#define LDQ 132
#define LDS 68
#define NTILES (KVLEN / 64)
#define ATT_SMEM ((5 * 64 * LDQ + 2 * 64 * LDS + 64) * 4)

__global__ __launch_bounds__(512) void attn_kernel(
    const float* __restrict__ cache_k, const float* __restrict__ cache_v)
{
    extern __shared__ __align__(16) float smem[];
    float* Qs    = smem;
    float* Kb[2] = { Qs + 64 * LDQ,     Qs + 2 * 64 * LDQ };
    float* Vb[2] = { Qs + 3 * 64 * LDQ, Qs + 4 * 64 * LDQ };
    float* Ss[2] = { Qs + 5 * 64 * LDQ, Qs + 5 * 64 * LDQ + 64 * LDS };
    float* lrow  = Qs + 5 * 64 * LDQ + 2 * 64 * LDS;

    const int b   = blockIdx.x >> 3;
    const int kvh = blockIdx.x & 7;
    const int tid = threadIdx.x;
    const int warp = tid >> 5;
    const bool isP = warp < 8;

    const uint32_t kaddr[2] = { smem_u32(Kb[0]), smem_u32(Kb[1]) };
    const uint32_t vaddr[2] = { smem_u32(Vb[0]), smem_u32(Vb[1]) };

    auto load_K = [&](int t, int bb2) {
        const int p0 = t * 64;
#pragma unroll
        for (int i = tid; i < 2048; i += 256) {
            int r = i >> 5, c16 = i & 31;
            int p = p0 + r;
            const float* srck;
            if (p < STARTP)
                srck = cache_k + (((size_t)b * KVLEN + p) * KV_ + kvh) * (size_t)HD_ + c16 * 4;
            else
                srck = g_qkv + (size_t)(b * 16 + p - STARTP) * NQKV + 4096 + kvh * 128 + c16 * 4;
            cp16(kaddr[bb2] + (uint32_t)(r * LDQ + c16 * 4) * 4u, srck);
        }
        cp_commit();
    };
    auto load_V = [&](int t, int bb2) {
        const int p0 = t * 64;
#pragma unroll
        for (int i = tid - 256; i < 2048; i += 256) {
            int r = i >> 5, c16 = i & 31;
            int p = p0 + r;
            const float* srcv;
            if (p < STARTP)
                srcv = cache_v + (((size_t)b * KVLEN + p) * KV_ + kvh) * (size_t)HD_ + c16 * 4;
            else
                srcv = g_qkv + (size_t)(b * 16 + p - STARTP) * NQKV + 5120 + kvh * 128 + c16 * 4;
            cp16(vaddr[bb2] + (uint32_t)(r * LDQ + c16 * 4) * 4u, srcv);
        }
        cp_commit();
    };

    if (isP) { load_K(0, 0); load_K(1, 1); }
    else     { load_V(0, 0); load_V(1, 1); }

    const float scale = 0.08838834764831845f;
    for (int i = tid; i < 64 * 32; i += 512) {
        int j = i >> 5, c = (i & 31) << 2;
        int s = j & 15, hr = j >> 4;
        float4 v = *reinterpret_cast<const float4*>(
            g_qkv + (size_t)(b * 16 + s) * NQKV + (kvh * 4 + hr) * HD_ + c);
        float* d = Qs + j * LDQ + c;
        d[0] = to_tf32(v.x * scale); d[1] = to_tf32(v.y * scale);
        d[2] = to_tf32(v.z * scale); d[3] = to_tf32(v.w * scale);
    }
    if (tid < 64) lrow[tid] = 0.0f;
    __syncthreads();

    // consumer accumulators at function scope (used after join)
    wmma::fragment<wmma::accumulator, 16, 16, 8, float> o_acc[4];
#pragma unroll
    for (int j = 0; j < 4; j++) wmma::fill_fragment(o_acc[j], 0.0f);

    if (isP) {
        // ------------- producer: QK^T + exp -------------
        const int wm = warp >> 1;      // 0..3, rows wm*16
        const int wn = warp & 1;       // 0..1, cols wn*32
        wmma::fragment<wmma::matrix_a, 16, 16, 8, wmma::precision::tf32, wmma::row_major> qf[16];
#pragma unroll
        for (int kk = 0; kk < 16; kk++)
            wmma::load_matrix_sync(qf[kk], Qs + (wm * 16) * LDQ + kk * 8, LDQ);

        for (int t = 0; t < NTILES; t++) {
            const int buf = t & 1;
            float* Kc = Kb[buf];
            float* Sb = Ss[buf];

            if (t + 2 < NTILES) cp_wait<1>(); else cp_wait<0>();
            NBAR_SYNC(5, 256);                    // K(t) visible to producer group
            if (t >= 2) NBAR_SYNC(3 + buf, 512);  // wait consumer recycle of Ss[buf]

            wmma::fragment<wmma::accumulator, 16, 16, 8, float> s_acc[2];
#pragma unroll
            for (int j = 0; j < 2; j++) wmma::fill_fragment(s_acc[j], 0.0f);
#pragma unroll
            for (int kk = 0; kk < 16; kk++) {
#pragma unroll
                for (int j = 0; j < 2; j++) {
                    wmma::fragment<wmma::matrix_b, 16, 16, 8, wmma::precision::tf32, wmma::col_major> bk;
                    wmma::load_matrix_sync(bk, Kc + (wn * 32 + j * 16) * LDQ + kk * 8, LDQ);
                    round_frag(bk);
                    wmma::mma_sync(s_acc[j], qf[kk], bk, s_acc[j]);
                }
            }
#pragma unroll
            for (int j = 0; j < 2; j++)
                wmma::store_matrix_sync(Sb + (wm * 16) * LDS + wn * 32 + j * 16,
                                        s_acc[j], LDS, wmma::mem_row_major);
            NBAR_SYNC(5, 256);                    // S stored; K[buf] free
            if (t + 2 < NTILES) load_K(t + 2, buf);

            // exp + mask + rowsum (256 producer threads, 16 cols each)
            {
                int r = tid >> 2, part = tid & 3;
                int lim = STARTP + (r & 15);
                float* row = Sb + r * LDS + part * 16;
                int pbase = t * 64 + part * 16;
                float sum = 0.0f;
#pragma unroll
                for (int c = 0; c < 16; c++) {
                    float v = row[c];
                    float pv = (pbase + c <= lim) ? __expf(v) : 0.0f;
                    sum += pv;
                    row[c] = to_tf32(pv);
                }
                sum += __shfl_xor_sync(0xffffffffu, sum, 1);
                sum += __shfl_xor_sync(0xffffffffu, sum, 2);
                if (part == 0) lrow[r] += sum;
            }
            NBAR_ARRIVE(1 + buf, 512);            // publish tile t (non-blocking)
        }
    } else {
        // ------------- consumer: PV -------------
        const int cw = warp - 8;
        const int wm = cw >> 1;        // 0..3, rows wm*16
        const int wn = cw & 1;         // 0..1, cols wn*64

        for (int t = 0; t < NTILES; t++) {
            const int buf = t & 1;
            float* Vc = Vb[buf];
            float* Sb = Ss[buf];

            if (t + 2 < NTILES) cp_wait<1>(); else cp_wait<0>();
            NBAR_SYNC(6, 256);                    // V(t) visible to consumer group
            NBAR_SYNC(1 + buf, 512);              // wait publish of tile t

#pragma unroll
            for (int kk = 0; kk < 8; kk++) {
                wmma::fragment<wmma::matrix_a, 16, 16, 8, wmma::precision::tf32, wmma::row_major> a;
                wmma::load_matrix_sync(a, Sb + (wm * 16) * LDS + kk * 8, LDS);
#pragma unroll
                for (int j = 0; j < 4; j++) {
                    wmma::fragment<wmma::matrix_b, 16, 16, 8, wmma::precision::tf32, wmma::row_major> bv;
                    wmma::load_matrix_sync(bv, Vc + (kk * 8) * LDQ + wn * 64 + j * 16, LDQ);
                    wmma::mma_sync(o_acc[j], a, bv, o_acc[j]);
                }
            }
            if (t + 2 < NTILES) {
                NBAR_ARRIVE(3 + buf, 512);        // recycle Ss[buf]/V[buf] (non-blocking)
                load_V(t + 2, buf);
            }
        }
    }

    __syncthreads();    // join both roles; lrow + all tiles complete

    float* Os = Kb[0];
    if (!isP) {
        const int cw = warp - 8;
        const int wm = cw >> 1;
        const int wn = cw & 1;
#pragma unroll
        for (int j = 0; j < 4; j++)
            wmma::store_matrix_sync(Os + (wm * 16) * LDQ + wn * 64 + j * 16,
                                    o_acc[j], LDQ, wmma::mem_row_major);
    }
    __syncthreads();    // Os visible to all

    for (int i = tid; i < 64 * 32; i += 512) {
        int j = i >> 5, c = (i & 31) << 2;
        int s = j & 15, hr = j >> 4;
        float inv = 1.0f / lrow[j];
        float4 v = *reinterpret_cast<float4*>(Os + j * LDQ + c);
        v.x = to_tf32(v.x * inv); v.y = to_tf32(v.y * inv);
        v.z = to_tf32(v.z * inv); v.w = to_tf32(v.w * inv);
        *reinterpret_cast<float4*>(
            g_attn + (size_t)(b * 16 + s) * D_ + (kvh * 4 + hr) * HD_ + c) = v;
    }
}

// ---------------------------------------------------------------------------
extern "C" void kernel_launch(void* const* d_in, const int* in_sizes, int n_in,
                              void* d_out, int out_size)
{
    const float* x       = (const float*)d_in[0];
    const float* fcos    = (const float*)d_in[1];
    const float* fsin    = (const float*)d_in[2];
    const float* cache_k = (const float*)d_in[4];
    const float* cache_v = (const float*)d_in[5];
    const float* wq = (const float*)d_in[6];
    const float* bq = (const float*)d_in[7];
    const float* wk = (const float*)d_in[8];
    const float* bk = (const float*)d_in[9];
    const float* wv = (const float*)d_in[10];
    const float* bv = (const float*)d_in[11];
    const float* wo = (const float*)d_in[12];
    const float* bo = (const float*)d_in[13];
    float* out = (float*)d_out;

    float *attnb, *partb;
    cudaGetSymbolAddress((void**)&attnb, g_attn);
    cudaGetSymbolAddress((void**)&partb, g_part);

    cudaFuncSetAttribute(gemm_splitk, cudaFuncAttributeMaxDynamicSharedMemorySize, G_SMEM);
    cudaFuncSetAttribute(attn_kernel, cudaFuncAttributeMaxDynamicSharedMemorySize, ATT_SMEM);

    const int FIN_TOTAL = T_ * (NQKV / 4);
    const int FIN_HALF  = FIN_TOTAL / 2;

    // 1: fused QKV projection, split-K=2 (384 CTAs)
    gemm_splitk<<<dim3(NQKV / 128, T_ / 64, 2), 256, G_SMEM>>>(
        x, wq, wk, wv, partb, NQKV, D_, 1);
    // 2+3: reduce partials + bias + RoPE (two halves)
    qkv_finish<<<FIN_HALF / 256, 256>>>(bq, bk, bv, fcos, fsin, 0);
    qkv_finish<<<FIN_HALF / 256, 256>>>(bq, bk, bv, fcos, fsin, FIN_HALF);
    // 4: attention (profiler slot)
    attn_kernel<<<B_ * KV_, 512, ATT_SMEM>>>(cache_k, cache_v);
    // 5: O projection, split-K=2 (256 CTAs)
    gemm_splitk<<<dim3(D_ / 128, T_ / 64, 2), 256, G_SMEM>>>(
        attnb, wo, wo, wo, partb, D_, D_, 0);
    // 6: reduce partials + bias -> out
    o_finish<<<(T_ * (D_ / 4) + 255) / 256, 256>>>(bo, out);
}